// round 7
// baseline (speedup 1.0000x reference)
#include <cuda_runtime.h>

// ConformalMetric: R = -2*exp(-2*Phi) * (lap(Phi) + 2*|grad(Phi)|^2)
// Phi = phi_pos - lambda*phi_neg, edge-clamped 6-point stencil, h=1.
// Shape (B,H,W,D) = (4,128,128,128), D contiguous.
//
// Round-7: round-4 structure (barrier-free H-march, packed f32x2, 40 warps/SM)
// + L2 residency via createpolicy/cache_hint (the inline .L2::evict_last
// qualifier needs 256-bit loads on sm_103a; the policy-register form works
// with .v2.u64). Inputs evict_last, output streamed with __stcs.

#define Bn 4
#define Hn 128
#define Wn 128
#define Dn 128
#define WSLAB 8     // W rows per block
#define CH 4        // H planes marched per block

typedef unsigned long long u64;

__device__ __forceinline__ u64 pk2(float lo, float hi) {
    u64 r; asm("mov.b64 %0, {%1, %2};" : "=l"(r) : "f"(lo), "f"(hi)); return r;
}
__device__ __forceinline__ void upk2(u64 v, float& lo, float& hi) {
    asm("mov.b64 {%0, %1}, %2;" : "=f"(lo), "=f"(hi) : "l"(v));
}
__device__ __forceinline__ u64 fma2(u64 a, u64 b, u64 c) {
    u64 r; asm("fma.rn.f32x2 %0, %1, %2, %3;" : "=l"(r) : "l"(a), "l"(b), "l"(c)); return r;
}
__device__ __forceinline__ u64 add2(u64 a, u64 b) {
    u64 r; asm("add.rn.f32x2 %0, %1, %2;" : "=l"(r) : "l"(a), "l"(b)); return r;
}
__device__ __forceinline__ u64 mul2(u64 a, u64 b) {
    u64 r; asm("mul.rn.f32x2 %0, %1, %2;" : "=l"(r) : "l"(a), "l"(b)); return r;
}
__device__ __forceinline__ float ex2f(float x) {
    float r; asm("ex2.approx.f32 %0, %1;" : "=f"(r) : "f"(x)); return r;
}
// evict_last access policy (covers all of L2's policy window)
__device__ __forceinline__ u64 mkpolicy_evict_last() {
    u64 p;
    asm("createpolicy.fractional.L2::evict_last.b64 %0, 1.0;" : "=l"(p));
    return p;
}
// 128-bit read-only load with L2 cache-hint policy
__device__ __forceinline__ void ldg_keep(const float* p, u64 pol, u64& a, u64& b) {
    asm("ld.global.nc.L2::cache_hint.v2.u64 {%0, %1}, [%2], %3;"
        : "=l"(a), "=l"(b) : "l"(p), "l"(pol));
}

struct P4 { u64 lo, hi; };   // 4 floats as two packed f32x2 (elems 0,1 | 2,3)

__global__ __launch_bounds__(256, 5) void conformal_l2p(
    const float* __restrict__ pos,
    const float* __restrict__ neg,
    const float* __restrict__ lam_p,
    float* __restrict__ out)
{
    const float lam = __ldg(lam_p);
    const u64 POL    = mkpolicy_evict_last();
    const u64 NEGLAM = pk2(-lam, -lam);
    const u64 NEG1   = pk2(-1.0f, -1.0f);
    const u64 NEG6   = pk2(-6.0f, -6.0f);
    const u64 HALF   = pk2(0.5f, 0.5f);
    const u64 N2L2E  = pk2(-2.8853900817779268f, -2.8853900817779268f); // -2*log2(e)
    const u64 NEG2   = pk2(-2.0f, -2.0f);

    const int tx = threadIdx.x;            // 0..31 -> d4 lane
    const int ty = threadIdx.y;            // 0..WSLAB-1 -> w row
    const int b  = blockIdx.z;
    const int h0 = blockIdx.y * CH;
    const int w  = blockIdx.x * WSLAB + ty;

    const int wm = (w > 0)      ? w - 1 : 0;
    const int wp = (w < Wn - 1) ? w + 1 : Wn - 1;

    const int base_b = b * Hn * Wn * Dn;
    const int dofs   = tx * 4;

    auto ldphi = [&](int hh, int ww) -> P4 {
        const int i = base_b + (hh * Wn + ww) * Dn + dofs;
        u64 p0, p1, n0, n1;
        ldg_keep(pos + i, POL, p0, p1);
        ldg_keep(neg + i, POL, n0, n1);
        P4 r;
        r.lo = fma2(n0, NEGLAM, p0);       // phi = pos - lam*neg (packed)
        r.hi = fma2(n1, NEGLAM, p1);
        return r;
    };

    // prologue: Phi(h0-1), Phi(h0)
    const int hm0 = (h0 > 0) ? h0 - 1 : 0;
    P4 Cm = ldphi(hm0, w);
    P4 Cc = ldphi(h0,  w);

#pragma unroll
    for (int hh = 0; hh < CH; ++hh) {
        const int h  = h0 + hh;
        const int hp = (h < Hn - 1) ? h + 1 : Hn - 1;

        // three independent plane loads (no barriers -> deep MLP)
        P4 Cp = ldphi(hp, w);    // Phi(h+1, w)
        P4 YM = ldphi(h,  wm);   // Phi(h, w-1) — L1/L2 hit
        P4 YP = ldphi(h,  wp);   // Phi(h, w+1) — L1/L2 hit

        // unpack center for shuffles / D-shifted pairs
        float cx, cy, cz, cw;
        upk2(Cc.lo, cx, cy);
        upk2(Cc.hi, cz, cw);

        float zm0 = __shfl_up_sync(0xffffffffu,  cw, 1);
        float zp3 = __shfl_down_sync(0xffffffffu, cx, 1);
        if (tx == 0)  zm0 = cx;   // clamp d=0
        if (tx == 31) zp3 = cw;   // clamp d=Dn-1

        // D-shifted packed vectors: zm={zm0,cx,cy,cz}, zp={cy,cz,cw,zp3}
        const u64 zm_lo = pk2(zm0, cx);
        const u64 mid   = pk2(cy, cz);     // zm.hi == zp.lo
        const u64 zp_hi = pk2(cw, zp3);

        float r0, r1, r2, r3;
#pragma unroll
        for (int half = 0; half < 2; ++half) {
            const u64 c  = half ? Cc.hi : Cc.lo;
            const u64 xm = half ? Cm.hi : Cm.lo;
            const u64 xp = half ? Cp.hi : Cp.lo;
            const u64 ym = half ? YM.hi : YM.lo;
            const u64 yp = half ? YP.hi : YP.lo;
            const u64 zm = half ? mid   : zm_lo;
            const u64 zp = half ? zp_hi : mid;

            const u64 dx = fma2(xm, NEG1, xp);           // xp - xm
            const u64 dy = fma2(ym, NEG1, yp);
            const u64 dz = fma2(zm, NEG1, zp);
            u64 sq = mul2(dz, dz);
            sq = fma2(dy, dy, sq);
            sq = fma2(dx, dx, sq);                       // sum d^2 = 4*grad_sq

            u64 lap = add2(add2(add2(xp, xm), add2(yp, ym)), add2(zp, zm));
            lap = fma2(c, NEG6, lap);                    // - 6c
            const u64 arg  = fma2(sq, HALF, lap);        // lap + 2*grad_sq
            const u64 m    = mul2(c, N2L2E);             // -2c*log2(e)
            const u64 narg = mul2(arg, NEG2);            // -2*arg

            float m0, m1, a0, a1;
            upk2(m, m0, m1);
            upk2(narg, a0, a1);
            const float e0 = ex2f(m0);                   // exp(-2c)
            const float e1 = ex2f(m1);
            if (half) { r2 = e0 * a0; r3 = e1 * a1; }
            else      { r0 = e0 * a0; r1 = e1 * a1; }
        }

        // streaming store: keep the write stream out of the inputs' L2 space
        const int oidx = base_b + (h * Wn + w) * Dn + dofs;
        __stcs(reinterpret_cast<float4*>(out + oidx),
               make_float4(r0, r1, r2, r3));

        Cm = Cc; Cc = Cp;
    }
}

extern "C" void kernel_launch(void* const* d_in, const int* in_sizes, int n_in,
                              void* d_out, int out_size)
{
    const float* pos = (const float*)d_in[0];  // phi_positive (B,H,W,D) f32
    const float* neg = (const float*)d_in[1];  // phi_negative (B,H,W,D) f32
    const float* lam = (const float*)d_in[2];  // lambda_repulsion (1,) f32
    float* out = (float*)d_out;

    dim3 block(32, WSLAB, 1);                   // 256 threads
    dim3 grid(Wn / WSLAB, Hn / CH, Bn);         // (16, 32, 4) = 2048 blocks
    conformal_l2p<<<grid, block>>>(pos, neg, lam, out);
}

// round 8
// speedup vs baseline: 1.0976x; 1.0976x over previous
#include <cuda_runtime.h>

// ConformalMetric: R = -2*exp(-2*Phi) * (lap(Phi) + 2*|grad(Phi)|^2)
// Phi = phi_pos - lambda*phi_neg, edge-clamped 6-point stencil, h=1.
// Shape (B,H,W,D) = (4,128,128,128), D contiguous.
//
// Round-8: 256-bit loads (LDG.256, inline .L2::evict_last), 16 lanes per
// D-row (8 floats/thread), each warp covers 2 adjacent W rows so the W+-1
// partner comes from shfl_xor(16) instead of global. The stencil only uses
// (yp-ym)^2 and (yp+ym), both symmetric, so neighbor identity is irrelevant.
// Global planes per iter: center(h+1) + one outside W row = 4 LDG.256.
// Packed f32x2 math, streaming stores.

#define Bn 4
#define Hn 128
#define Wn 128
#define Dn 128
#define WSLAB 16    // W rows per block (ty)
#define CH 4        // H planes marched per block

typedef unsigned long long u64;

__device__ __forceinline__ u64 pk2(float lo, float hi) {
    u64 r; asm("mov.b64 %0, {%1, %2};" : "=l"(r) : "f"(lo), "f"(hi)); return r;
}
__device__ __forceinline__ void upk2(u64 v, float& lo, float& hi) {
    asm("mov.b64 {%0, %1}, %2;" : "=f"(lo), "=f"(hi) : "l"(v));
}
__device__ __forceinline__ u64 fma2(u64 a, u64 b, u64 c) {
    u64 r; asm("fma.rn.f32x2 %0, %1, %2, %3;" : "=l"(r) : "l"(a), "l"(b), "l"(c)); return r;
}
__device__ __forceinline__ u64 add2(u64 a, u64 b) {
    u64 r; asm("add.rn.f32x2 %0, %1, %2;" : "=l"(r) : "l"(a), "l"(b)); return r;
}
__device__ __forceinline__ u64 mul2(u64 a, u64 b) {
    u64 r; asm("mul.rn.f32x2 %0, %1, %2;" : "=l"(r) : "l"(a), "l"(b)); return r;
}
__device__ __forceinline__ float ex2f(float x) {
    float r; asm("ex2.approx.f32 %0, %1;" : "=f"(r) : "f"(x)); return r;
}
// 256-bit read-only load, keep-resident-in-L2 (inline qualifier, no policy reg)
__device__ __forceinline__ void ldg256(const float* p, u64& a, u64& b, u64& c, u64& d) {
    asm("ld.global.nc.L2::evict_last.v4.b64 {%0, %1, %2, %3}, [%4];"
        : "=l"(a), "=l"(b), "=l"(c), "=l"(d) : "l"(p));
}
// 128-bit streaming store of two packed f32x2
__device__ __forceinline__ void stg_cs(float* p, u64 a, u64 b) {
    asm volatile("st.global.cs.v2.b64 [%0], {%1, %2};" :: "l"(p), "l"(a), "l"(b) : "memory");
}

struct P8 { u64 q[4]; };   // 8 floats as four packed f32x2

__global__ __launch_bounds__(256, 4) void conformal_v8(
    const float* __restrict__ pos,
    const float* __restrict__ neg,
    const float* __restrict__ lam_p,
    float* __restrict__ out)
{
    const float lam = __ldg(lam_p);
    const u64 NEGLAM = pk2(-lam, -lam);
    const u64 NEG1   = pk2(-1.0f, -1.0f);
    const u64 NEG6   = pk2(-6.0f, -6.0f);
    const u64 HALF   = pk2(0.5f, 0.5f);
    const u64 N2L2E  = pk2(-2.8853900817779268f, -2.8853900817779268f); // -2*log2(e)
    const u64 NEG2   = pk2(-2.0f, -2.0f);

    const int tx = threadIdx.x;            // 0..15 -> 8-float D segment
    const int ty = threadIdx.y;            // 0..15 -> W row
    const int b  = blockIdx.z;
    const int h0 = blockIdx.y * CH;
    const int w  = blockIdx.x * WSLAB + ty;

    // outside-warp W neighbor: even rows fetch w-1, odd rows fetch w+1
    const bool evenrow = (ty & 1) == 0;
    int wnb = evenrow ? w - 1 : w + 1;
    wnb = (wnb < 0) ? 0 : ((wnb > Wn - 1) ? Wn - 1 : wnb);

    const int base_b = b * Hn * Wn * Dn;
    const int dofs   = tx * 8;

    auto ldphi = [&](int hh, int ww) -> P8 {
        const int i = base_b + (hh * Wn + ww) * Dn + dofs;
        u64 p0, p1, p2, p3, n0, n1, n2, n3;
        ldg256(pos + i, p0, p1, p2, p3);
        ldg256(neg + i, n0, n1, n2, n3);
        P8 r;
        r.q[0] = fma2(n0, NEGLAM, p0);
        r.q[1] = fma2(n1, NEGLAM, p1);
        r.q[2] = fma2(n2, NEGLAM, p2);
        r.q[3] = fma2(n3, NEGLAM, p3);
        return r;
    };

    // prologue: Phi(h0-1), Phi(h0) for own column
    const int hm0 = (h0 > 0) ? h0 - 1 : 0;
    P8 Cm = ldphi(hm0, w);
    P8 Cc = ldphi(h0,  w);

#pragma unroll
    for (int hh = 0; hh < CH; ++hh) {
        const int h  = h0 + hh;
        const int hp = (h < Hn - 1) ? h + 1 : Hn - 1;

        // 4 independent LDG.256 front-batched
        P8 Cp = ldphi(hp, w);      // Phi(h+1, w)
        P8 Nb = ldphi(h,  wnb);    // outside W neighbor of plane h

        // partner W row (the other half-warp) via shuffle
        P8 Ot;
#pragma unroll
        for (int k = 0; k < 4; ++k)
            Ot.q[k] = __shfl_xor_sync(0xffffffffu, Cc.q[k], 16);

        // unpack center for D shifts
        float e0, e1, e2, e3, e4, e5, e6, e7;
        upk2(Cc.q[0], e0, e1);
        upk2(Cc.q[1], e2, e3);
        upk2(Cc.q[2], e4, e5);
        upk2(Cc.q[3], e6, e7);

        // D-edge exchange within the 16-lane row segment
        float zm0 = __shfl_up_sync(0xffffffffu,  e7, 1, 16);
        float zp7 = __shfl_down_sync(0xffffffffu, e0, 1, 16);
        if (tx == 0)  zm0 = e0;    // clamp d=0
        if (tx == 15) zp7 = e7;    // clamp d=Dn-1

        const u64 A  = pk2(zm0, e0);
        const u64 M1 = pk2(e1, e2);
        const u64 M2 = pk2(e3, e4);
        const u64 M3 = pk2(e5, e6);
        const u64 Bq = pk2(e7, zp7);
        const u64 zmv[4] = {A,  M1, M2, M3};
        const u64 zpv[4] = {M1, M2, M3, Bq};

        u64 rq[4];
#pragma unroll
        for (int k = 0; k < 4; ++k) {
            const u64 c  = Cc.q[k];
            const u64 xm = Cm.q[k];
            const u64 xp = Cp.q[k];
            const u64 ya = Nb.q[k];   // one W neighbor (identity irrelevant)
            const u64 yb = Ot.q[k];   // the other
            const u64 zm = zmv[k];
            const u64 zp = zpv[k];

            const u64 dx = fma2(xm, NEG1, xp);           // xp - xm
            const u64 dy = fma2(ya, NEG1, yb);           // +-(yp - ym)
            const u64 dz = fma2(zm, NEG1, zp);
            u64 sq = mul2(dz, dz);
            sq = fma2(dy, dy, sq);
            sq = fma2(dx, dx, sq);                       // sum d^2 = 4*grad_sq

            u64 lap = add2(add2(add2(xp, xm), add2(ya, yb)), add2(zp, zm));
            lap = fma2(c, NEG6, lap);                    // - 6c
            const u64 arg  = fma2(sq, HALF, lap);        // lap + 2*grad_sq
            const u64 m    = mul2(c, N2L2E);             // -2c*log2(e)
            const u64 narg = mul2(arg, NEG2);            // -2*arg

            float m0, m1, a0, a1;
            upk2(m, m0, m1);
            upk2(narg, a0, a1);
            rq[k] = pk2(ex2f(m0) * a0, ex2f(m1) * a1);
        }

        float* op = out + base_b + (h * Wn + w) * Dn + dofs;
        stg_cs(op,     rq[0], rq[1]);
        stg_cs(op + 4, rq[2], rq[3]);

        Cm = Cc; Cc = Cp;
    }
}

extern "C" void kernel_launch(void* const* d_in, const int* in_sizes, int n_in,
                              void* d_out, int out_size)
{
    const float* pos = (const float*)d_in[0];  // phi_positive (B,H,W,D) f32
    const float* neg = (const float*)d_in[1];  // phi_negative (B,H,W,D) f32
    const float* lam = (const float*)d_in[2];  // lambda_repulsion (1,) f32
    float* out = (float*)d_out;

    dim3 block(16, WSLAB, 1);                   // 256 threads
    dim3 grid(Wn / WSLAB, Hn / CH, Bn);         // (8, 32, 4) = 1024 blocks
    conformal_v8<<<grid, block>>>(pos, neg, lam, out);
}

// round 9
// speedup vs baseline: 1.3688x; 1.2471x over previous
#include <cuda_runtime.h>

// ConformalMetric: R = -2*exp(-2*Phi) * (lap(Phi) + 2*|grad(Phi)|^2)
// Phi = phi_pos - lambda*phi_neg, edge-clamped 6-point stencil, h=1.
// Shape (B,H,W,D) = (4,128,128,128), D contiguous.
//
// Round-9: exact round-4 structure (best: 16.9us) + software pipeline on the
// center plane: Cp(h+1) is prefetched one iteration ahead, so the only
// DRAM-missing stream gets a full iteration of load->use distance. W+-1
// neighbor loads stay same-iteration (they're L1/L2 hits). Packed f32x2
// math, 40 warps/SM, streaming stores.

#define Bn 4
#define Hn 128
#define Wn 128
#define Dn 128
#define WSLAB 8     // W rows per block
#define CH 4        // H planes marched per block

typedef unsigned long long u64;

__device__ __forceinline__ u64 pk2(float lo, float hi) {
    u64 r; asm("mov.b64 %0, {%1, %2};" : "=l"(r) : "f"(lo), "f"(hi)); return r;
}
__device__ __forceinline__ void upk2(u64 v, float& lo, float& hi) {
    asm("mov.b64 {%0, %1}, %2;" : "=f"(lo), "=f"(hi) : "l"(v));
}
__device__ __forceinline__ u64 fma2(u64 a, u64 b, u64 c) {
    u64 r; asm("fma.rn.f32x2 %0, %1, %2, %3;" : "=l"(r) : "l"(a), "l"(b), "l"(c)); return r;
}
__device__ __forceinline__ u64 add2(u64 a, u64 b) {
    u64 r; asm("add.rn.f32x2 %0, %1, %2;" : "=l"(r) : "l"(a), "l"(b)); return r;
}
__device__ __forceinline__ u64 mul2(u64 a, u64 b) {
    u64 r; asm("mul.rn.f32x2 %0, %1, %2;" : "=l"(r) : "l"(a), "l"(b)); return r;
}
__device__ __forceinline__ float ex2f(float x) {
    float r; asm("ex2.approx.f32 %0, %1;" : "=f"(r) : "f"(x)); return r;
}

struct P4 { u64 lo, hi; };   // 4 floats as two packed f32x2 (elems 0,1 | 2,3)

__global__ __launch_bounds__(256, 5) void conformal_pipe(
    const float* __restrict__ pos,
    const float* __restrict__ neg,
    const float* __restrict__ lam_p,
    float* __restrict__ out)
{
    const float lam = __ldg(lam_p);
    const u64 NEGLAM = pk2(-lam, -lam);
    const u64 NEG1   = pk2(-1.0f, -1.0f);
    const u64 NEG6   = pk2(-6.0f, -6.0f);
    const u64 HALF   = pk2(0.5f, 0.5f);
    const u64 N2L2E  = pk2(-2.8853900817779268f, -2.8853900817779268f); // -2*log2(e)
    const u64 NEG2   = pk2(-2.0f, -2.0f);

    const int tx = threadIdx.x;            // 0..31 -> d4 lane
    const int ty = threadIdx.y;            // 0..WSLAB-1 -> w row
    const int b  = blockIdx.z;
    const int h0 = blockIdx.y * CH;
    const int w  = blockIdx.x * WSLAB + ty;

    const int wm = (w > 0)      ? w - 1 : 0;
    const int wp = (w < Wn - 1) ? w + 1 : Wn - 1;

    const int base_b = b * Hn * Wn * Dn;
    const int dofs   = tx * 4;

    auto ldphi = [&](int hh, int ww) -> P4 {
        const int i = base_b + (hh * Wn + ww) * Dn + dofs;
        const ulonglong2 P = *reinterpret_cast<const ulonglong2*>(pos + i);
        const ulonglong2 N = *reinterpret_cast<const ulonglong2*>(neg + i);
        P4 r;
        r.lo = fma2(N.x, NEGLAM, P.x);     // phi = pos - lam*neg (packed)
        r.hi = fma2(N.y, NEGLAM, P.y);
        return r;
    };

    // prologue: Phi(h0-1), Phi(h0), and prefetched Phi(h0+1)
    const int hm0 = (h0 > 0) ? h0 - 1 : 0;
    P4 Cm = ldphi(hm0, w);
    P4 Cc = ldphi(h0,  w);
    P4 Cp = ldphi(h0 + 1, w);              // h0 <= Hn-CH, so h0+1 < Hn

#pragma unroll
    for (int hh = 0; hh < CH; ++hh) {
        const int h   = h0 + hh;
        const int hp2 = (h + 2 < Hn) ? h + 2 : Hn - 1;  // next iteration's Cp

        // issue all of this iteration's new loads up front:
        // Cp_next is the DRAM stream (used NEXT iteration -> latency hidden),
        // YM/YP are L1/L2 hits (used this iteration).
        P4 Cpn = ldphi(hp2, w);
        P4 YM  = ldphi(h,  wm);
        P4 YP  = ldphi(h,  wp);

        // unpack center for shuffles / D-shifted pairs
        float cx, cy, cz, cw;
        upk2(Cc.lo, cx, cy);
        upk2(Cc.hi, cz, cw);

        float zm0 = __shfl_up_sync(0xffffffffu,  cw, 1);
        float zp3 = __shfl_down_sync(0xffffffffu, cx, 1);
        if (tx == 0)  zm0 = cx;   // clamp d=0
        if (tx == 31) zp3 = cw;   // clamp d=Dn-1

        // D-shifted packed vectors: zm={zm0,cx,cy,cz}, zp={cy,cz,cw,zp3}
        const u64 zm_lo = pk2(zm0, cx);
        const u64 mid   = pk2(cy, cz);     // zm.hi == zp.lo
        const u64 zp_hi = pk2(cw, zp3);

        float r0, r1, r2, r3;
#pragma unroll
        for (int half = 0; half < 2; ++half) {
            const u64 c  = half ? Cc.hi : Cc.lo;
            const u64 xm = half ? Cm.hi : Cm.lo;
            const u64 xp = half ? Cp.hi : Cp.lo;
            const u64 ym = half ? YM.hi : YM.lo;
            const u64 yp = half ? YP.hi : YP.lo;
            const u64 zm = half ? mid   : zm_lo;
            const u64 zp = half ? zp_hi : mid;

            const u64 dx = fma2(xm, NEG1, xp);           // xp - xm
            const u64 dy = fma2(ym, NEG1, yp);
            const u64 dz = fma2(zm, NEG1, zp);
            u64 sq = mul2(dz, dz);
            sq = fma2(dy, dy, sq);
            sq = fma2(dx, dx, sq);                       // sum d^2 = 4*grad_sq

            u64 lap = add2(add2(add2(xp, xm), add2(yp, ym)), add2(zp, zm));
            lap = fma2(c, NEG6, lap);                    // - 6c
            const u64 arg  = fma2(sq, HALF, lap);        // lap + 2*grad_sq
            const u64 m    = mul2(c, N2L2E);             // -2c*log2(e)
            const u64 narg = mul2(arg, NEG2);            // -2*arg

            float m0, m1, a0, a1;
            upk2(m, m0, m1);
            upk2(narg, a0, a1);
            const float e0 = ex2f(m0);                   // exp(-2c)
            const float e1 = ex2f(m1);
            if (half) { r2 = e0 * a0; r3 = e1 * a1; }
            else      { r0 = e0 * a0; r1 = e1 * a1; }
        }

        // streaming store: keep the write stream from evicting inputs
        const int oidx = base_b + (h * Wn + w) * Dn + dofs;
        __stcs(reinterpret_cast<float4*>(out + oidx),
               make_float4(r0, r1, r2, r3));

        Cm = Cc; Cc = Cp; Cp = Cpn;
    }
}

extern "C" void kernel_launch(void* const* d_in, const int* in_sizes, int n_in,
                              void* d_out, int out_size)
{
    const float* pos = (const float*)d_in[0];  // phi_positive (B,H,W,D) f32
    const float* neg = (const float*)d_in[1];  // phi_negative (B,H,W,D) f32
    const float* lam = (const float*)d_in[2];  // lambda_repulsion (1,) f32
    float* out = (float*)d_out;

    dim3 block(32, WSLAB, 1);                   // 256 threads
    dim3 grid(Wn / WSLAB, Hn / CH, Bn);         // (16, 32, 4) = 2048 blocks
    conformal_pipe<<<grid, block>>>(pos, neg, lam, out);
}